// round 11
// baseline (speedup 1.0000x reference)
#include <cuda_runtime.h>
#include <cuda_bf16.h>
#include <cstdint>

#define NNODES 50000
#define EDGES  800000
#define DHID   128
#define RREL   8
#define KACC   (RREL * DHID)   /* 1024 */
#define KTOT   (KACC + DHID)   /* 1152 */
#define NR     (NNODES * RREL) /* 400000 buckets */
#define NBLK1  ((NR + 1023) / 1024)  /* 391 */

#define BM   128
#define KC   64
#define NCH  (KTOT / KC)       /* 18 */
#define LDSB 72
#define TILE_BYTES (128 * LDSB * 2)
#define STAGE_BYTES (4 * TILE_BYTES)
#define SMEM_BYTES (2 * STAGE_BYTES)
#define SMAX 8                 /* prefetched edges per bucket */

// ---------------------------------------------------------------------------
// Scratch
// ---------------------------------------------------------------------------
__device__ float g_h[(size_t)NNODES * DHID];              // layer-1 output
__device__ __nv_bfloat16 g_Bth[2][(size_t)DHID * KTOT];
__device__ __nv_bfloat16 g_Btl[2][(size_t)DHID * KTOT];
__device__ int g_off[NR];      // CSR bucket starts (exclusive scan)
__device__ int g_cnt[NR];      // counts -> cursor -> bucket ENDS after fill
__device__ int g_csr[EDGES];   // src row OFFSET (src*DHID) per slot
__device__ int g_bsum[512];

// ---------------------------------------------------------------------------
// PTX helpers (standard PTX only — harness targets sm_103, no "a" features)
// ---------------------------------------------------------------------------
__device__ __forceinline__ uint32_t smem_u32(const void* p) {
    uint32_t a;
    asm("{ .reg .u64 t; cvta.to.shared.u64 t, %1; cvt.u32.u64 %0, t; }"
        : "=r"(a) : "l"(p));
    return a;
}
__device__ __forceinline__ void sts128(uint32_t a, uint4 v) {
    asm volatile("st.shared.v4.b32 [%0], {%1,%2,%3,%4};"
                 :: "r"(a), "r"(v.x), "r"(v.y), "r"(v.z), "r"(v.w) : "memory");
}
__device__ __forceinline__ void split2(float x0, float x1,
                                       uint32_t& hw, uint32_t& lw) {
    asm("cvt.rn.bf16x2.f32 %0, %1, %2;" : "=r"(hw) : "f"(x1), "f"(x0));
    float h0 = __uint_as_float(hw << 16);
    float h1 = __uint_as_float(hw & 0xFFFF0000u);
    float r0 = x0 - h0;
    float r1 = x1 - h1;
    asm("cvt.rn.bf16x2.f32 %0, %1, %2;" : "=r"(lw) : "f"(r1), "f"(r0));
}
__device__ __forceinline__ void ldm_x4(uint32_t* r, uint32_t addr) {
    asm volatile("ldmatrix.sync.aligned.m8n8.x4.shared.b16 {%0,%1,%2,%3}, [%4];"
                 : "=r"(r[0]), "=r"(r[1]), "=r"(r[2]), "=r"(r[3]) : "r"(addr));
}
__device__ __forceinline__ void mma_bf16(float* c, const uint32_t* a,
                                         const uint32_t* b) {
    asm volatile("mma.sync.aligned.m16n8k16.row.col.f32.bf16.bf16.f32 "
                 "{%0,%1,%2,%3}, {%4,%5,%6,%7}, {%8,%9}, {%0,%1,%2,%3};"
                 : "+f"(c[0]), "+f"(c[1]), "+f"(c[2]), "+f"(c[3])
                 : "r"(a[0]), "r"(a[1]), "r"(a[2]), "r"(a[3]),
                   "r"(b[0]), "r"(b[1]));
}

// ---------------------------------------------------------------------------
// CSR build kernels
// ---------------------------------------------------------------------------
__global__ void zero_cnt_kernel() {
    int i = blockIdx.x * blockDim.x + threadIdx.x;   // i in [0, NR/4)
    if (i * 4 < NR)
        *reinterpret_cast<int4*>(g_cnt + i * 4) = make_int4(0, 0, 0, 0);
}
__global__ void hist_kernel(const int* __restrict__ dst,
                            const int* __restrict__ et) {
    int e = blockIdx.x * blockDim.x + threadIdx.x;
    if (e < EDGES) atomicAdd(&g_cnt[dst[e] * RREL + et[e]], 1);
}
__global__ void scan1_kernel() {
    __shared__ int wsum[8];
    int tid = threadIdx.x;
    int base = blockIdx.x * 1024 + tid * 4;
    int v[4];
#pragma unroll
    for (int q = 0; q < 4; q++)
        v[q] = (base + q < NR) ? g_cnt[base + q] : 0;
    int s = v[0] + v[1] + v[2] + v[3];
    int lane = tid & 31, w = tid >> 5;
    int inc = s;
#pragma unroll
    for (int d = 1; d < 32; d <<= 1) {
        int t = __shfl_up_sync(0xFFFFFFFFu, inc, d);
        if (lane >= d) inc += t;
    }
    if (lane == 31) wsum[w] = inc;
    __syncthreads();
    if (tid == 0) {
        int a = 0;
#pragma unroll
        for (int i = 0; i < 8; i++) { int t = wsum[i]; wsum[i] = a; a += t; }
        g_bsum[blockIdx.x] = a;
    }
    __syncthreads();
    int ex = inc - s + wsum[w];
#pragma unroll
    for (int q = 0; q < 4; q++) {
        if (base + q < NR) g_off[base + q] = ex;
        ex += v[q];
    }
}
__global__ void scan2_kernel() {      // 512 threads, scans g_bsum[NBLK1]
    __shared__ int sm[512];
    int tid = threadIdx.x;
    int v = (tid < NBLK1) ? g_bsum[tid] : 0;
    sm[tid] = v;
    __syncthreads();
    for (int d = 1; d < 512; d <<= 1) {
        int t = (tid >= d) ? sm[tid - d] : 0;
        __syncthreads();
        sm[tid] += t;
        __syncthreads();
    }
    if (tid < NBLK1) g_bsum[tid] = sm[tid] - v;   // exclusive
}
__global__ void scan3_kernel() {
    int i = blockIdx.x * blockDim.x + threadIdx.x;
    if (i < NR) {
        int o = g_off[i] + g_bsum[i >> 10];
        g_off[i] = o;
        g_cnt[i] = o;      // cursor for fill; becomes bucket END after fill
    }
}
__global__ void fill_kernel(const int* __restrict__ src,
                            const int* __restrict__ dst,
                            const int* __restrict__ et) {
    int e = blockIdx.x * blockDim.x + threadIdx.x;
    if (e < EDGES) {
        int b = dst[e] * RREL + et[e];
        int pos = atomicAdd(&g_cnt[b], 1);
        g_csr[pos] = src[e] * DHID;    // prescaled row offset
    }
}

// ---------------------------------------------------------------------------
// Pre-split weights: Bt[l][n][k] = Bstack_l[k][n]  (hi/lo bf16)
// ---------------------------------------------------------------------------
__global__ void prep_B_kernel(const float* __restrict__ W1,
                              const float* __restrict__ L1,
                              const float* __restrict__ W2,
                              const float* __restrict__ L2) {
    int t = blockIdx.x * blockDim.x + threadIdx.x;
    if (t >= 2 * DHID * KTOT) return;
    int l   = t / (DHID * KTOT);
    int rem = t % (DHID * KTOT);
    int n = rem / KTOT;
    int k = rem % KTOT;
    const float* W = l ? W2 : W1;
    const float* L = l ? L2 : L1;
    float v = (k < KACC) ? W[(size_t)k * DHID + n]
                         : L[(size_t)(k - KACC) * DHID + n];
    __nv_bfloat16 h = __float2bfloat16(v);
    float r = v - __bfloat162float(h);
    g_Bth[l][rem] = h;
    g_Btl[l][rem] = __float2bfloat16(r);
}

// ---------------------------------------------------------------------------
// Fused gather + warp-MMA GEMM, double-buffered, index-prefetched.
//   A row n, chunk c<16 (rel r=c>>1): sum_{e in CSR[n*8+r]} x[src_e][slice]
//   chunks 16,17: self-loop slice of input row.
// Chunks 2r and 2r+1 share a bucket: indices loaded once (even c only).
// ---------------------------------------------------------------------------
__global__ void __launch_bounds__(256, 1)
gemm_mma_kernel(const float* __restrict__ xin, int xin_is_h, int layer,
                const float* __restrict__ bias,
                float* __restrict__ out, int out_is_h, int do_norm) {
    extern __shared__ char smem[];
    uint32_t sb = smem_u32(smem);

    int tid  = threadIdx.x;
    int wid  = tid >> 5;
    int lane = tid & 31;
    int wm   = wid & 3;
    int wn   = wid >> 2;
    int row0 = blockIdx.x * BM;

    const float* xp = xin_is_h ? g_h : xin;
    float*       op = out_is_h ? g_h : out;
    const __nv_bfloat16* Bhg = g_Bth[layer];
    const __nv_bfloat16* Blg = g_Btl[layer];

    int r    = tid >> 1;     // loader row 0..127
    int half = tid & 1;      // 32-wide sub-slice within the 64-k chunk
    int gr   = row0 + r;
    bool valid = gr < NNODES;
    int grc = valid ? gr : 0;

    float acc[2][8][4];
#pragma unroll
    for (int mt = 0; mt < 2; mt++)
#pragma unroll
        for (int nt = 0; nt < 8; nt++)
#pragma unroll
            for (int j = 0; j < 4; j++) acc[mt][nt][j] = 0.f;

    uint32_t aoff0 = (uint32_t)((wm * 32 + (lane & 15)) * LDSB * 2
                                + (lane >> 4) * 8 * 2);
    uint32_t boff0 = (uint32_t)((wn * 64 + ((lane >> 4) & 1) * 8 + (lane & 7))
                                * LDSB * 2 + ((lane >> 3) & 1) * 16);
    uint32_t sbase = (uint32_t)(r * LDSB * 2 + half * 64);

    // ---- lookahead registers ----
    uint4 bhf[4], blf[4];    // B hi/lo for the chunk about to be produced
    int rs = 0, re = 0;      // CSR range (persists across the chunk pair)
    int idxs[SMAX];          // prefetched row offsets (persists across pair)

    auto prefetch_meta = [&](int c) {
        int k0 = c * KC;
        const uint4* bhp = (const uint4*)(Bhg + (size_t)r * KTOT + k0 + half * 32);
        const uint4* blp = (const uint4*)(Blg + (size_t)r * KTOT + k0 + half * 32);
#pragma unroll
        for (int q = 0; q < 4; q++) { bhf[q] = bhp[q]; blf[q] = blp[q]; }
        if (c < 16) {
            if ((c & 1) == 0) {          // even chunk: new bucket
                if (valid) {
                    int b = grc * RREL + (c >> 1);
                    rs = g_off[b];
                    re = g_cnt[b];
                } else {
                    rs = re = 0;
                }
#pragma unroll
                for (int q = 0; q < SMAX; q++)
                    idxs[q] = (rs + q < re) ? g_csr[rs + q] : 0;
            }
            // odd chunk: same bucket — rs/re/idxs already loaded
        } else {
            rs = re = 0;
        }
    };

    auto produce_store = [&](int c, int s) {
        float4 sv[8];
#pragma unroll
        for (int q = 0; q < 8; q++) sv[q] = make_float4(0.f, 0.f, 0.f, 0.f);
        int ih = c & 1;
        const float* xb = xp + ih * 64 + half * 32;
        if (c < 16) {
            int cnt = re - rs;
            // prefetched edges: indices in regs, loads issue back-to-back
#pragma unroll
            for (int q = 0; q < SMAX; q++) {
                if (q < cnt) {
                    const float4* p = (const float4*)(xb + idxs[q]);
#pragma unroll
                    for (int u = 0; u < 8; u++) {
                        float4 t = p[u];
                        sv[u].x += t.x; sv[u].y += t.y;
                        sv[u].z += t.z; sv[u].w += t.w;
                    }
                }
            }
            // rare overflow (>SMAX edges): serial fallback
            for (int e = rs + SMAX; e < re; e++) {
                const float4* p = (const float4*)(xb + g_csr[e]);
#pragma unroll
                for (int u = 0; u < 8; u++) {
                    float4 t = p[u];
                    sv[u].x += t.x; sv[u].y += t.y;
                    sv[u].z += t.z; sv[u].w += t.w;
                }
            }
        } else if (valid) {
            const float4* p = (const float4*)(xb + (size_t)grc * DHID);
#pragma unroll
            for (int q = 0; q < 8; q++) sv[q] = p[q];
        }
        // split + store A and B
        uint32_t st = sb + (uint32_t)s * STAGE_BYTES;
#pragma unroll
        for (int q = 0; q < 4; q++) {
            float4 f0 = sv[2 * q], f1 = sv[2 * q + 1];
            uint4 hv, lv;
            split2(f0.x, f0.y, hv.x, lv.x);
            split2(f0.z, f0.w, hv.y, lv.y);
            split2(f1.x, f1.y, hv.z, lv.z);
            split2(f1.z, f1.w, hv.w, lv.w);
            uint32_t o = sbase + q * 16;
            sts128(st + o, hv);
            sts128(st + TILE_BYTES + o, lv);
            sts128(st + 2 * TILE_BYTES + o, bhf[q]);
            sts128(st + 3 * TILE_BYTES + o, blf[q]);
        }
    };

    // ---- prologue ----
    prefetch_meta(0);
    produce_store(0, 0);
    prefetch_meta(1);
    __syncthreads();

#pragma unroll 1
    for (int c = 0; c < NCH; ++c) {
        int s = c & 1;
        uint32_t st = sb + (uint32_t)s * STAGE_BYTES;

#pragma unroll
        for (int ks = 0; ks < 4; ++ks) {
            uint32_t ka = (uint32_t)(ks * 32);
            uint32_t ah[2][4], al[2][4];
#pragma unroll
            for (int mt = 0; mt < 2; mt++) {
                uint32_t ao = aoff0 + (uint32_t)(mt * 16 * LDSB * 2) + ka;
                ldm_x4(ah[mt], st + ao);
                ldm_x4(al[mt], st + TILE_BYTES + ao);
            }
#pragma unroll
            for (int ntp = 0; ntp < 4; ntp++) {
                uint32_t bo = boff0 + (uint32_t)(ntp * 16 * LDSB * 2) + ka;
                uint32_t bh4[4], bl4[4];
                ldm_x4(bh4, st + 2 * TILE_BYTES + bo);
                ldm_x4(bl4, st + 3 * TILE_BYTES + bo);
#pragma unroll
                for (int mt = 0; mt < 2; mt++) {
                    mma_bf16(acc[mt][2 * ntp],     ah[mt], bh4);
                    mma_bf16(acc[mt][2 * ntp],     ah[mt], bl4);
                    mma_bf16(acc[mt][2 * ntp],     al[mt], bh4);
                    mma_bf16(acc[mt][2 * ntp + 1], ah[mt], bh4 + 2);
                    mma_bf16(acc[mt][2 * ntp + 1], ah[mt], bl4 + 2);
                    mma_bf16(acc[mt][2 * ntp + 1], al[mt], bh4 + 2);
                }
            }
        }

        if (c + 1 < NCH) {
            produce_store(c + 1, s ^ 1);
            if (c + 2 < NCH) prefetch_meta(c + 2);
        }
        __syncthreads();
    }

    // ---- epilogue ----
    int qrow = lane >> 2;
    int qcol = (lane & 3) * 2;

#pragma unroll
    for (int nt = 0; nt < 8; nt++) {
        int c0 = wn * 64 + nt * 8 + qcol;
        float bx = bias[c0], by = bias[c0 + 1];
#pragma unroll
        for (int mt = 0; mt < 2; mt++) {
            acc[mt][nt][0] += bx; acc[mt][nt][1] += by;
            acc[mt][nt][2] += bx; acc[mt][nt][3] += by;
        }
    }

    if (!do_norm) {
#pragma unroll
        for (int mt = 0; mt < 2; mt++)
#pragma unroll
            for (int h = 0; h < 2; h++) {
                int row = wm * 32 + mt * 16 + h * 8 + qrow;
                int g = row0 + row;
                if (g < NNODES) {
#pragma unroll
                    for (int nt = 0; nt < 8; nt++) {
                        int c0 = wn * 64 + nt * 8 + qcol;
                        float2 v = make_float2(fmaxf(acc[mt][nt][h * 2], 0.f),
                                               fmaxf(acc[mt][nt][h * 2 + 1], 0.f));
                        *(float2*)(op + (size_t)g * DHID + c0) = v;
                    }
                }
            }
    } else {
        float* rowsq = (float*)smem;
        if (tid < BM) rowsq[tid] = 0.f;
        __syncthreads();
        float s2[2][2];
#pragma unroll
        for (int mt = 0; mt < 2; mt++)
#pragma unroll
            for (int h = 0; h < 2; h++) {
                float t = 0.f;
#pragma unroll
                for (int nt = 0; nt < 8; nt++) {
                    t += acc[mt][nt][h * 2] * acc[mt][nt][h * 2]
                       + acc[mt][nt][h * 2 + 1] * acc[mt][nt][h * 2 + 1];
                }
                t += __shfl_xor_sync(0xFFFFFFFFu, t, 1);
                t += __shfl_xor_sync(0xFFFFFFFFu, t, 2);
                s2[mt][h] = t;
            }
        if ((lane & 3) == 0) {
#pragma unroll
            for (int mt = 0; mt < 2; mt++)
#pragma unroll
                for (int h = 0; h < 2; h++)
                    atomicAdd(&rowsq[wm * 32 + mt * 16 + h * 8 + qrow], s2[mt][h]);
        }
        __syncthreads();
#pragma unroll
        for (int mt = 0; mt < 2; mt++)
#pragma unroll
            for (int h = 0; h < 2; h++) {
                int row = wm * 32 + mt * 16 + h * 8 + qrow;
                int g = row0 + row;
                if (g < NNODES) {
                    float inv = 1.0f / fmaxf(sqrtf(rowsq[row]), 1e-12f);
#pragma unroll
                    for (int nt = 0; nt < 8; nt++) {
                        int c0 = wn * 64 + nt * 8 + qcol;
                        float2 v = make_float2(acc[mt][nt][h * 2] * inv,
                                               acc[mt][nt][h * 2 + 1] * inv);
                        *(float2*)(op + (size_t)g * DHID + c0) = v;
                    }
                }
            }
    }
}

// ---------------------------------------------------------------------------
// Launch: CSR build (once, shared by both layers) -> prep -> gemm1 -> gemm2
// ---------------------------------------------------------------------------
extern "C" void kernel_launch(void* const* d_in, const int* in_sizes, int n_in,
                              void* d_out, int out_size) {
    const float* x      = (const float*)d_in[0];
    const float* W1     = (const float*)d_in[1];
    const float* loopW1 = (const float*)d_in[2];
    const float* b1     = (const float*)d_in[3];
    const float* W2     = (const float*)d_in[4];
    const float* loopW2 = (const float*)d_in[5];
    const float* b2     = (const float*)d_in[6];
    const int*   src    = (const int*)d_in[7];
    const int*   dst    = (const int*)d_in[8];
    const int*   et     = (const int*)d_in[9];
    float* out = (float*)d_out;

    cudaFuncSetAttribute(gemm_mma_kernel,
                         cudaFuncAttributeMaxDynamicSharedMemorySize, SMEM_BYTES);

    int eblocks = (EDGES + 255) / 256;          // 3125
    int gblocks = (NNODES + BM - 1) / BM;       // 391
    int pblocks = (2 * DHID * KTOT + 255) / 256;

    // CSR build
    zero_cnt_kernel<<<(NR / 4 + 255) / 256, 256>>>();
    hist_kernel<<<eblocks, 256>>>(dst, et);
    scan1_kernel<<<NBLK1, 256>>>();
    scan2_kernel<<<1, 512>>>();
    scan3_kernel<<<(NR + 255) / 256, 256>>>();
    fill_kernel<<<eblocks, 256>>>(src, dst, et);

    prep_B_kernel<<<pblocks, 256>>>(W1, loopW1, W2, loopW2);

    // Layer 1: relu( gather(x) @ W + x @ loopW + b1 ) -> g_h
    gemm_mma_kernel<<<gblocks, 256, SMEM_BYTES>>>(x, 0, 0, b1, nullptr, 1, 0);
    // Layer 2: normalize( gather(g_h) @ W + g_h @ loopW + b2 ) -> out
    gemm_mma_kernel<<<gblocks, 256, SMEM_BYTES>>>(nullptr, 1, 1, b2, out, 0, 1);
}